// round 1
// baseline (speedup 1.0000x reference)
#include <cuda_runtime.h>

// ---------------- problem constants ----------------
#define BB   4
#define HH   8
#define NN   2048
#define BHN  (BB*HH)          // 32
#define DHD  16               // head dim == v head dim
#define MROWS (BB*NN)         // 8192

// ---------------- scratch (static device, no allocs) ----------------
__device__ float g_qs[BHN * NN * DHD];      // [bh][n][16], log2e*scaling folded in
__device__ float g_ks[BHN * NN * DHD];      // [bh][n][16]
__device__ float g_vs[BHN * NN * DHD];      // [bh][n][16]
__device__ float g_ctx[MROWS * 128];        // [b*N+n][h*16+e]  (row-major, ready for out proj)

// ---------------- helpers ----------------
__device__ __forceinline__ float ex2f_fast(float x) {
    float y;
    asm("ex2.approx.ftz.f32 %0, %1;" : "=f"(y) : "f"(x));
    return y;
}
__device__ __forceinline__ float dot4acc(float4 a, float4 b, float t) {
    t = fmaf(a.x, b.x, t); t = fmaf(a.y, b.y, t);
    t = fmaf(a.z, b.z, t); t = fmaf(a.w, b.w, t);
    return t;
}
__device__ __forceinline__ void fma4(float4& o, float p, float4 v) {
    o.x = fmaf(p, v.x, o.x); o.y = fmaf(p, v.y, o.y);
    o.z = fmaf(p, v.z, o.z); o.w = fmaf(p, v.w, o.w);
}
__device__ __forceinline__ void mul4(float4& o, float c) {
    o.x *= c; o.y *= c; o.z *= c; o.w *= c;
}

// ---------------- Q/K projection ----------------
// out = (A[8192,128] @ W[128,128]^T + bias) * alpha, scattered to [bh][n][16].
// blockIdx.y selects q (y=0, alpha=scaling*log2e) vs k (y=1, alpha=1).
__global__ void __launch_bounds__(128) projqk_kernel(
    const float* __restrict__ Aq, const float* __restrict__ Ak,
    const float* __restrict__ Wq, const float* __restrict__ Wk,
    const float* __restrict__ bq, const float* __restrict__ bk,
    float alpha_q)
{
    const int TM = 32;
    __shared__ float As[TM][128];
    __shared__ float Ws[32][129];   // W^T chunk: Ws[kk][c]

    const bool is_k = (blockIdx.y != 0);
    const float* A    = is_k ? Ak : Aq;
    const float* W    = is_k ? Wk : Wq;
    const float* bias = is_k ? bk : bq;
    float*       outp = is_k ? g_ks : g_qs;
    const float alpha = is_k ? 1.0f : alpha_q;

    const int r0 = blockIdx.x * TM;
    const int c  = threadIdx.x;

    // stage A tile (32x128 fp32, coalesced float4)
    {
        const float4* Ag = (const float4*)(A + (size_t)r0 * 128);
        float4* Asv = (float4*)&As[0][0];
        #pragma unroll
        for (int i = 0; i < 8; i++) Asv[c + 128 * i] = Ag[c + 128 * i];
    }

    float acc[TM];
    #pragma unroll
    for (int r = 0; r < TM; r++) acc[r] = 0.f;

    for (int k0 = 0; k0 < 128; k0 += 32) {
        __syncthreads();
        // stage W chunk transposed: thread c loads W[c][k0..k0+31]
        const float4* wg = (const float4*)(W + c * 128 + k0);
        #pragma unroll
        for (int i = 0; i < 8; i++) {
            float4 w4 = wg[i];
            Ws[i * 4 + 0][c] = w4.x; Ws[i * 4 + 1][c] = w4.y;
            Ws[i * 4 + 2][c] = w4.z; Ws[i * 4 + 3][c] = w4.w;
        }
        __syncthreads();
        #pragma unroll
        for (int kk = 0; kk < 32; kk += 4) {
            const float w0 = Ws[kk + 0][c], w1 = Ws[kk + 1][c];
            const float w2 = Ws[kk + 2][c], w3 = Ws[kk + 3][c];
            #pragma unroll
            for (int r = 0; r < TM; r++) {
                float4 a4 = *(const float4*)&As[r][k0 + kk];
                float t = acc[r];
                t = fmaf(a4.x, w0, t); t = fmaf(a4.y, w1, t);
                t = fmaf(a4.z, w2, t); t = fmaf(a4.w, w3, t);
                acc[r] = t;
            }
        }
    }

    const float bc = bias[c];
    const int h = c >> 4, d = c & 15;
    #pragma unroll
    for (int r = 0; r < TM; r++) {
        const int row = r0 + r;
        const int b = row >> 11, n = row & 2047;
        outp[(((size_t)(b * HH + h) * NN + n) << 4) + d] = (acc[r] + bc) * alpha;
    }
}

// ---------------- V projection (K=16, tiny) ----------------
__global__ void __launch_bounds__(256) projv_kernel(
    const float* __restrict__ value, const float* __restrict__ Wv,
    const float* __restrict__ bv)
{
    const int o = blockIdx.x * 256 + threadIdx.x;   // over 8192*128
    const int r = o >> 7, c = o & 127;
    const float4* a = (const float4*)(value + ((size_t)r << 4));
    const float4* w = (const float4*)(Wv + ((size_t)c << 4));
    float4 a0 = a[0], a1 = a[1], a2 = a[2], a3 = a[3];
    float4 w0 = w[0], w1 = w[1], w2 = w[2], w3 = w[3];
    float t = bv[c];
    t = dot4acc(a0, w0, t); t = dot4acc(a1, w1, t);
    t = dot4acc(a2, w2, t); t = dot4acc(a3, w3, t);
    const int b = r >> 11, n = r & 2047, h = c >> 4, d = c & 15;
    g_vs[(((size_t)(b * HH + h) * NN + n) << 4) + d] = t;
}

// ---------------- fused flash attention (fp32, streaming softmax) ----------------
// grid: 512 CTAs = 32 (b,h) x 16 q-tiles of 128 rows; 128 threads, 1 q-row/thread.
// Softmax in log2 domain (log2e*scaling folded into q) -> p = ex2(s - m).
__global__ void __launch_bounds__(128) attn_kernel()
{
    const int TK = 128;
    const int bh  = blockIdx.x >> 4;
    const int rt  = blockIdx.x & 15;
    const int row = rt * 128 + threadIdx.x;

    const float4* qp = (const float4*)(g_qs + (((size_t)bh * NN + row) << 4));
    const float4 q0 = qp[0], q1 = qp[1], q2 = qp[2], q3 = qp[3];

    __shared__ float4 Ks[TK * 4];
    __shared__ float4 Vs[TK * 4];

    float m = -1e30f, l = 0.f;
    float4 o0 = {0,0,0,0}, o1 = {0,0,0,0}, o2 = {0,0,0,0}, o3 = {0,0,0,0};

    const float4* Kbase = (const float4*)(g_ks + ((size_t)bh * NN << 4));
    const float4* Vbase = (const float4*)(g_vs + ((size_t)bh * NN << 4));

    for (int t0 = 0; t0 < NN; t0 += TK) {
        __syncthreads();
        #pragma unroll
        for (int i = 0; i < 4; i++) {
            Ks[threadIdx.x + 128 * i] = Kbase[t0 * 4 + threadIdx.x + 128 * i];
            Vs[threadIdx.x + 128 * i] = Vbase[t0 * 4 + threadIdx.x + 128 * i];
        }
        __syncthreads();

        #pragma unroll 1
        for (int jc = 0; jc < TK; jc += 16) {
            float s[16];
            float cm = -1e30f;
            #pragma unroll
            for (int jj = 0; jj < 16; jj++) {
                const int j = jc + jj;
                float t = q0.x * Ks[4*j].x;
                t = fmaf(q0.y, Ks[4*j].y, t);
                t = fmaf(q0.z, Ks[4*j].z, t);
                t = fmaf(q0.w, Ks[4*j].w, t);
                t = dot4acc(q1, Ks[4*j+1], t);
                t = dot4acc(q2, Ks[4*j+2], t);
                t = dot4acc(q3, Ks[4*j+3], t);
                s[jj] = t;
                cm = fmaxf(cm, t);
            }
            const float mnew = fmaxf(m, cm);
            const float corr = ex2f_fast(m - mnew);
            m = mnew;
            l *= corr;
            mul4(o0, corr); mul4(o1, corr); mul4(o2, corr); mul4(o3, corr);
            #pragma unroll
            for (int jj = 0; jj < 16; jj++) {
                const int j = jc + jj;
                const float p = ex2f_fast(s[jj] - m);
                l += p;
                fma4(o0, p, Vs[4*j+0]);
                fma4(o1, p, Vs[4*j+1]);
                fma4(o2, p, Vs[4*j+2]);
                fma4(o3, p, Vs[4*j+3]);
            }
        }
    }

    const float inv = 1.0f / l;
    mul4(o0, inv); mul4(o1, inv); mul4(o2, inv); mul4(o3, inv);

    const int b = bh >> 3, h = bh & 7;
    float4* op = (float4*)(g_ctx + ((size_t)(b * NN + row) << 7) + h * DHD);
    op[0] = o0; op[1] = o1; op[2] = o2; op[3] = o3;
}

// ---------------- output projection: ctx[8192,128] @ Wo[16,128]^T + bo ----------------
__global__ void __launch_bounds__(256) outproj_kernel(
    const float* __restrict__ Wo, const float* __restrict__ bo,
    float* __restrict__ out)
{
    __shared__ float Cs[16][128];
    __shared__ float Ws[16][132];   // padded (132 % 4 == 0 keeps float4 alignment)
    const int r0 = blockIdx.x * 16;

    const float4* cg = (const float4*)(g_ctx + ((size_t)r0 << 7));
    float4* csv = (float4*)&Cs[0][0];
    csv[threadIdx.x]       = cg[threadIdx.x];
    csv[threadIdx.x + 256] = cg[threadIdx.x + 256];
    for (int i = threadIdx.x; i < 2048; i += 256) Ws[i >> 7][i & 127] = Wo[i];
    __syncthreads();

    const int r = threadIdx.x >> 4, c = threadIdx.x & 15;
    float acc = bo[c];
    #pragma unroll
    for (int kk = 0; kk < 128; kk += 4) {
        float4 a = *(const float4*)&Cs[r][kk];
        float4 w = *(const float4*)&Ws[c][kk];
        acc = dot4acc(a, w, acc);
    }
    out[((size_t)(r0 + r) << 4) + c] = acc;
}

// ---------------- launcher ----------------
extern "C" void kernel_launch(void* const* d_in, const int* in_sizes, int n_in,
                              void* d_out, int out_size)
{
    const float* query = (const float*)d_in[0];
    const float* key   = (const float*)d_in[1];
    const float* value = (const float*)d_in[2];
    const float* Wq    = (const float*)d_in[3];
    const float* bq    = (const float*)d_in[4];
    const float* Wk    = (const float*)d_in[5];
    const float* bk    = (const float*)d_in[6];
    const float* Wv    = (const float*)d_in[7];
    const float* bv    = (const float*)d_in[8];
    const float* Wo    = (const float*)d_in[9];
    const float* bo    = (const float*)d_in[10];
    float* out = (float*)d_out;

    const float LOG2E = 1.4426950408889634f;
    const float alpha_q = 0.25f * LOG2E;   // head_dim^-0.5 * log2(e), folded into q

    dim3 gqk(MROWS / 32, 2);
    projqk_kernel<<<gqk, 128>>>(query, key, Wq, Wk, bq, bk, alpha_q);
    projv_kernel<<<(MROWS * 128) / 256, 256>>>(value, Wv, bv);
    attn_kernel<<<BHN * (NN / 128), 128>>>();
    outproj_kernel<<<MROWS / 16, 256>>>(Wo, bo, out);
}